// round 4
// baseline (speedup 1.0000x reference)
#include <cuda_runtime.h>
#include <math.h>

#define BATCH 512
#define TT    2048
#define INP   32
#define H     256
#define DTC   0.1f
#define EPSC  1e-5f
#define BB    4
#define GRID  (BATCH / BB)   /* 128 blocks */
#define NT    512            /* 2 groups x 256 */

// Transposed-interleaved weight scratch: layout [k/4][j][k&3] per matrix.
// Order: Wattn0, Wattn1, Wrec0, Wrec1, Win1, Wskip, Win0
#define WOFF_A0 0
#define WOFF_A1 (1 * H * H)
#define WOFF_R0 (2 * H * H)
#define WOFF_R1 (3 * H * H)
#define WOFF_I1 (4 * H * H)
#define WOFF_SK (5 * H * H)
#define WOFF_I0 (6 * H * H)
__device__ __align__(16) float g_Wt[6 * H * H + INP * H];

__device__ __forceinline__ float sigmoidf_(float v) {
    return 1.0f / (1.0f + expf(-v));
}

// ---- packed f32x2 helpers ------------------------------------------------
__device__ __forceinline__ unsigned long long dup2(float w) {
    unsigned long long d;
    asm("mov.b64 %0, {%1, %1};" : "=l"(d) : "f"(w));
    return d;
}
__device__ __forceinline__ void ffma2(unsigned long long& d,
                                      unsigned long long a,
                                      unsigned long long b) {
    asm("fma.rn.f32x2 %0, %1, %2, %0;" : "+l"(d) : "l"(a), "l"(b));
}
__device__ __forceinline__ float2 unpk(unsigned long long v) {
    float2 r;
    asm("mov.b64 {%0, %1}, %2;" : "=f"(r.x), "=f"(r.y) : "l"(v));
    return r;
}

// Block-wide reduction over 16 warps of NV per-thread values -> stat[0..NV-1].
template <int NV>
__device__ __forceinline__ void block_reduce(float* vals, float (*red)[16], float* stat) {
    #pragma unroll
    for (int o = 16; o > 0; o >>= 1) {
        #pragma unroll
        for (int i = 0; i < NV; i++)
            vals[i] += __shfl_xor_sync(0xffffffffu, vals[i], o);
    }
    int w = threadIdx.x >> 5, l = threadIdx.x & 31;
    if (l == 0) {
        #pragma unroll
        for (int i = 0; i < NV; i++) red[w][i] = vals[i];
    }
    __syncthreads();
    if (threadIdx.x < NV) {
        float a = 0.f;
        #pragma unroll
        for (int w2 = 0; w2 < 16; w2++) a += red[w2][threadIdx.x];
        stat[threadIdx.x] = a;
    }
    __syncthreads();
}

// One [4,4*N4] x [4*N4, unit j] GEMM column. Weights from transposed scratch
// (coalesced LDG.128), h from SMEM broadcast LDS.128, 4-way acc ILP.
// acc[0..3]: interleaved f32x2 accumulators; result row pair p = acc[p] + acc[p+2].
template <int N4>
__device__ __forceinline__ void gemm_one(const float4* __restrict__ wp,
                                         const ulonglong2* __restrict__ hA,
                                         unsigned long long* acc) {
    float4 w0 = __ldg(wp);
    ulonglong2 ha = hA[0], hb = hA[1], hc = hA[2], hd = hA[3];
    #pragma unroll 4
    for (int c = 0; c < N4; c++) {
        float4 wc = w0;
        ulonglong2 a = ha, b = hb, d = hc, e = hd;
        if (c + 1 < N4) {
            w0 = __ldg(wp + (c + 1) * (H / 4) * 4);   // next float4 row: stride H floats? no:
        }
        // NOTE: stride fixed below via pointer math in caller-visible constant
        if (c + 1 < N4) {
            ha = hA[4 * c + 4]; hb = hA[4 * c + 5];
            hc = hA[4 * c + 6]; hd = hA[4 * c + 7];
        }
        unsigned long long w;
        w = dup2(wc.x); ffma2(acc[0], a.x, w); ffma2(acc[1], a.y, w);
        w = dup2(wc.y); ffma2(acc[2], b.x, w); ffma2(acc[3], b.y, w);
        w = dup2(wc.z); ffma2(acc[0], d.x, w); ffma2(acc[1], d.y, w);
        w = dup2(wc.w); ffma2(acc[2], e.x, w); ffma2(acc[3], e.y, w);
    }
}

__device__ __forceinline__ void acc_final(const unsigned long long* acc, float* r) {
    float2 lo = unpk(acc[0]), lo2 = unpk(acc[2]);
    float2 hi = unpk(acc[1]), hi2 = unpk(acc[3]);
    r[0] = lo.x + lo2.x; r[1] = lo.y + lo2.y;
    r[2] = hi.x + hi2.x; r[3] = hi.y + hi2.y;
}

// ---------------------------------------------------------------------------
// Kernel 0: transpose weights into [k/4][j][k&3] interleaved layout.
// ---------------------------------------------------------------------------
__global__ void transpose_kernel(
    const float* __restrict__ A0, const float* __restrict__ A1,
    const float* __restrict__ R0, const float* __restrict__ R1,
    const float* __restrict__ I1, const float* __restrict__ SK,
    const float* __restrict__ I0)
{
    int idx = blockIdx.x * blockDim.x + threadIdx.x;
    const int BIG = 6 * H * H;
    if (idx < BIG) {
        int m = idx >> 16, rem = idx & 65535;
        int k = rem >> 8, j = rem & 255;
        const float* src = (m == 0) ? A0 : (m == 1) ? A1 : (m == 2) ? R0
                         : (m == 3) ? R1 : (m == 4) ? I1 : SK;
        g_Wt[(m << 16) + (k >> 2) * (H * 4) + j * 4 + (k & 3)] = src[rem];
    } else if (idx < BIG + INP * H) {
        int rem = idx - BIG;
        int k = rem >> 8, j = rem & 255;
        g_Wt[BIG + (k >> 2) * (H * 4) + j * 4 + (k & 3)] = I0[rem];
    }
}

// ---------------------------------------------------------------------------
// Kernel 1: ew0[b,t] = mask * sigmoid([x_t, x_{t-1}] @ Wev0 + bev0)
// ---------------------------------------------------------------------------
__global__ void ew0_kernel(const float* __restrict__ x,
                           const float* __restrict__ Wev0,
                           const float* __restrict__ bev0,
                           float* __restrict__ ew0_out) {
    int idx = blockIdx.x * blockDim.x + threadIdx.x;
    if (idx >= BATCH * TT) return;
    int t = idx & (TT - 1);
    float r = 0.f;
    if (t > 0) {
        const float* xc = x + (size_t)idx * INP;
        const float* xp = xc - INP;
        float s = bev0[0];
        #pragma unroll
        for (int i = 0; i < INP; i++) s += xc[i] * Wev0[i];
        #pragma unroll
        for (int i = 0; i < INP; i++) s += xp[i] * Wev0[INP + i];
        r = sigmoidf_(s);
    }
    ew0_out[idx] = r;
}

// ---------------------------------------------------------------------------
// Kernel 2: persistent recurrence. 512 threads = 2 gemm-groups x 256 units.
// Group 0 (warps 0-7):  attn0, in0, rec0, in1  + layer-0 cell/LN + ew1.
// Group 1 (warps 8-15): attn1, rec1, skip      + layer-1 cell/LN + out.
// ---------------------------------------------------------------------------
__global__ __launch_bounds__(NT, 1) void liquid_kernel(
    const float* __restrict__ x,
    const float* __restrict__ bin0,  const float* __restrict__ brec0,
    const float* __restrict__ battn0,
    const float* __restrict__ tau0,  const float* __restrict__ gamma0, const float* __restrict__ beta0,
    const float* __restrict__ bin1,  const float* __restrict__ brec1,
    const float* __restrict__ battn1,
    const float* __restrict__ Wev1,  const float* __restrict__ bev1,
    const float* __restrict__ tau1,  const float* __restrict__ gamma1, const float* __restrict__ beta1,
    const float* __restrict__ bskip,
    const float* __restrict__ Wout,  const float* __restrict__ bout,
    float* __restrict__ out,
    const float* __restrict__ ew0_all,
    float* __restrict__ ew1_all)
{
    __shared__ __align__(16) float h0p[2][H][4];   // layer-0 hidden (ping-pong)
    __shared__ __align__(16) float h1p[2][H][4];   // layer-1 hidden (ping-pong)
    __shared__ __align__(16) float ha0p[H][4];     // h0 * attn0
    __shared__ __align__(16) float ha1p[H][4];     // h1 * attn1
    __shared__ __align__(16) float i1t[H][4];      // tanh(h0n @ Win1 + bin1)
    __shared__ __align__(16) float xp[INP][4];
    __shared__ float red_s[16][16];
    __shared__ float stat_s[16];
    __shared__ float ew1_s[BB];

    const int tid  = threadIdx.x;
    const int g    = tid >> 8;        // gemm-group (warp-aligned)
    const int j    = tid & 255;       // hidden unit
    const int row0 = blockIdx.x * BB;

    // ---- per-group constants ----
    float c_battn, c_brec, it, c_g, c_b;
    float c_bin0 = 0.f, c_bin1 = 0.f, wv1a = 0.f, wv1b = 0.f, c_bev1 = 0.f;
    float c_bskip = 0.f, c_wout = 0.f;
    if (g == 0) {
        c_battn = battn0[j]; c_brec = brec0[j];
        it = DTC / fminf(fmaxf(tau0[j], 0.1f), 10.0f);
        c_g = gamma0[j]; c_b = beta0[j];
        c_bin0 = bin0[j]; c_bin1 = bin1[j];
        wv1a = Wev1[j]; wv1b = Wev1[H + j]; c_bev1 = bev1[0];
    } else {
        c_battn = battn1[j]; c_brec = brec1[j];
        it = DTC / fminf(fmaxf(tau1[j], 0.1f), 10.0f);
        c_g = gamma1[j]; c_b = beta1[j];
        c_bskip = bskip[j]; c_wout = Wout[j];
    }
    const float gw = c_g * wv1a;   // g0_j * wa_j (group0 only; 0 in group1)

    // Fold-constants for ew1 logit: C2 = sum_j g0*wa, C3 = sum_j b0*wa
    {
        float cc[2] = { (g == 0) ? gw : 0.f, (g == 0) ? c_b * wv1a : 0.f };
        block_reduce<2>(cc, red_s, stat_s);
    }
    const float C2 = stat_s[0], C3 = stat_s[1];

    // Weight bases (transposed layout), offset by unit j
    const float4* wB = (const float4*)(g_Wt + (g ? WOFF_A1 : WOFF_A0)) + j;
    const float4* wC = (const float4*)(g_Wt + (g ? WOFF_R1 : WOFF_R0)) + j;
    const float4* wE = (const float4*)(g_Wt + (g ? WOFF_SK : WOFF_I1)) + j;
    const float4* wI = (const float4*)(g_Wt + WOFF_I0) + j;

    float h0own[BB] = {0.f, 0.f, 0.f, 0.f};
    float h1own[BB] = {0.f, 0.f, 0.f, 0.f};
    if (g == 0) *(float4*)&h0p[0][j][0] = make_float4(0.f, 0.f, 0.f, 0.f);
    else        *(float4*)&h1p[0][j][0] = make_float4(0.f, 0.f, 0.f, 0.f);
    __syncthreads();

    float t_rc1[BB];   // group1: tanh(rec1)
    float sk[BB];      // group1: skip

    for (int t = 0; t < TT; t++) {
        const int cur = t & 1, nxt = cur ^ 1;

        // ---- Stage A ----
        float e0r[BB];
        if (g == 0) {
            #pragma unroll
            for (int r = 0; r < BB; r++)
                e0r[r] = ew0_all[(size_t)(row0 + r) * TT + t];
        }
        if (tid < INP) {
            float4 xv;
            xv.x = x[((size_t)(row0 + 0) * TT + t) * INP + tid];
            xv.y = x[((size_t)(row0 + 1) * TT + t) * INP + tid];
            xv.z = x[((size_t)(row0 + 2) * TT + t) * INP + tid];
            xv.w = x[((size_t)(row0 + 3) * TT + t) * INP + tid];
            *(float4*)&xp[tid][0] = xv;
        }
        __syncthreads();   // orders prev-iter h writes

        // ---- Stage B: group0 attn0 (+in0), group1 attn1 ----
        float i0t[BB];
        {
            unsigned long long acc[4];
            acc[0] = acc[1] = dup2(c_battn); acc[2] = acc[3] = 0ull;
            const ulonglong2* hsrc = (const ulonglong2*)(g ? &h1p[cur][0][0] : &h0p[cur][0][0]);
            gemm_one<H / 4>(wB, hsrc, acc);
            float av[4]; acc_final(acc, av);

            if (g == 0) {
                unsigned long long ia[4];
                ia[0] = ia[1] = dup2(c_bin0); ia[2] = ia[3] = 0ull;
                gemm_one<INP / 4>(wI, (const ulonglong2*)&xp[0][0], ia);
                float iv[4]; acc_final(ia, iv);
                #pragma unroll
                for (int r = 0; r < BB; r++) i0t[r] = tanhf(iv[r]);
                *(float4*)&ha0p[j][0] = make_float4(
                    h0own[0] * sigmoidf_(av[0]), h0own[1] * sigmoidf_(av[1]),
                    h0own[2] * sigmoidf_(av[2]), h0own[3] * sigmoidf_(av[3]));
            } else {
                *(float4*)&ha1p[j][0] = make_float4(
                    h1own[0] * sigmoidf_(av[0]), h1own[1] * sigmoidf_(av[1]),
                    h1own[2] * sigmoidf_(av[2]), h1own[3] * sigmoidf_(av[3]));
            }
        }
        __syncthreads();

        // ---- Stage C: group0 rec0, group1 rec1 ----
        float rc0[BB];
        {
            unsigned long long acc[4];
            acc[0] = acc[1] = dup2(c_brec); acc[2] = acc[3] = 0ull;
            const ulonglong2* hsrc = (const ulonglong2*)(g ? &ha1p[0][0] : &ha0p[0][0]);
            gemm_one<H / 4>(wC, hsrc, acc);
            float rv[4]; acc_final(acc, rv);
            if (g == 0) {
                #pragma unroll
                for (int r = 0; r < BB; r++) rc0[r] = rv[r];
            } else {
                #pragma unroll
                for (int r = 0; r < BB; r++) t_rc1[r] = tanhf(rv[r]);
            }
        }

        // ---- Stage D: layer-0 cell + LN + folded ew1 logit (group0 data) ----
        float v0[BB], vals[16];
        #pragma unroll
        for (int i = 0; i < 16; i++) vals[i] = 0.f;
        if (g == 0) {
            #pragma unroll
            for (int r = 0; r < BB; r++) {
                float h = h0own[r];
                v0[r] = h + it * (-h + i0t[r] + tanhf(rc0[r])) * (1.f + e0r[r]);
                vals[4 * r + 0] = v0[r];
                vals[4 * r + 1] = v0[r] * v0[r];
                vals[4 * r + 2] = v0[r] * gw;
                vals[4 * r + 3] = h * wv1b;
            }
        }
        block_reduce<16>(vals, red_s, stat_s);

        if (g == 0) {
            float h0n[BB];
            #pragma unroll
            for (int r = 0; r < BB; r++) {
                float mu  = stat_s[4 * r] * (1.f / H);
                float var = stat_s[4 * r + 1] * (1.f / H) - mu * mu;
                h0n[r] = (v0[r] - mu) * rsqrtf(var + EPSC) * c_g + c_b;
                h0own[r] = h0n[r];
            }
            *(float4*)&h0p[nxt][j][0] = make_float4(h0n[0], h0n[1], h0n[2], h0n[3]);
            if (j < BB) {
                int r = j;
                float mu  = stat_s[4 * r] * (1.f / H);
                float var = stat_s[4 * r + 1] * (1.f / H) - mu * mu;
                float rs  = rsqrtf(var + EPSC);
                float lg  = rs * (stat_s[4 * r + 2] - mu * C2) + C3 + stat_s[4 * r + 3] + c_bev1;
                float e   = (t > 0) ? sigmoidf_(lg) : 0.f;
                ew1_s[r]  = e;
                ew1_all[(size_t)(row0 + r) * TT + t] = e;
            }
        }
        __syncthreads();   // h0p[nxt] + ew1_s visible

        // ---- Stage E: group0 in1, group1 skip (both read h0p[nxt]) ----
        {
            unsigned long long acc[4];
            acc[0] = acc[1] = dup2(g ? c_bskip : c_bin1); acc[2] = acc[3] = 0ull;
            gemm_one<H / 4>(wE, (const ulonglong2*)&h0p[nxt][0][0], acc);
            float ev[4]; acc_final(acc, ev);
            if (g == 0) {
                *(float4*)&i1t[j][0] = make_float4(
                    tanhf(ev[0]), tanhf(ev[1]), tanhf(ev[2]), tanhf(ev[3]));
            } else {
                #pragma unroll
                for (int r = 0; r < BB; r++) sk[r] = ev[r];
            }
        }
        __syncthreads();

        // ---- Stage F: layer-1 cell + LN + skip (group1 data) ----
        float v1[BB], vf[8];
        #pragma unroll
        for (int i = 0; i < 8; i++) vf[i] = 0.f;
        if (g == 1) {
            float4 i1v = *(const float4*)&i1t[j][0];
            float iarr[4] = { i1v.x, i1v.y, i1v.z, i1v.w };
            #pragma unroll
            for (int r = 0; r < BB; r++) {
                float h = h1own[r];
                v1[r] = h + it * (-h + iarr[r] + t_rc1[r]) * (1.f + ew1_s[r]);
                vf[2 * r]     = v1[r];
                vf[2 * r + 1] = v1[r] * v1[r];
            }
        }
        block_reduce<8>(vf, red_s, stat_s);
        if (g == 1) {
            #pragma unroll
            for (int r = 0; r < BB; r++) {
                float mu  = stat_s[2 * r] * (1.f / H);
                float var = stat_s[2 * r + 1] * (1.f / H) - mu * mu;
                h1own[r] = (v1[r] - mu) * rsqrtf(var + EPSC) * c_g + c_b + sk[r];
            }
            *(float4*)&h1p[nxt][j][0] = make_float4(h1own[0], h1own[1], h1own[2], h1own[3]);
        }
        // next iteration's Stage-A sync orders these writes
    }

    // ---- Final readout: out[b] = h1 @ Wout + bout ----
    __syncthreads();
    float oc[BB];
    #pragma unroll
    for (int r = 0; r < BB; r++) oc[r] = (g == 1) ? h1own[r] * c_wout : 0.f;
    block_reduce<4>(oc, red_s, stat_s);
    if (tid < BB) out[row0 + tid] = stat_s[tid] + bout[0];
}

extern "C" void kernel_launch(void* const* d_in, const int* in_sizes, int n_in,
                              void* d_out, int out_size) {
    const float* x      = (const float*)d_in[0];
    const float* Win0   = (const float*)d_in[1];
    const float* bin0   = (const float*)d_in[2];
    const float* Wrec0  = (const float*)d_in[3];
    const float* brec0  = (const float*)d_in[4];
    const float* Wattn0 = (const float*)d_in[5];
    const float* battn0 = (const float*)d_in[6];
    const float* Wev0   = (const float*)d_in[7];
    const float* bev0   = (const float*)d_in[8];
    const float* tau0   = (const float*)d_in[9];
    const float* gamma0 = (const float*)d_in[10];
    const float* beta0  = (const float*)d_in[11];
    const float* Win1   = (const float*)d_in[12];
    const float* bin1   = (const float*)d_in[13];
    const float* Wrec1  = (const float*)d_in[14];
    const float* brec1  = (const float*)d_in[15];
    const float* Wattn1 = (const float*)d_in[16];
    const float* battn1 = (const float*)d_in[17];
    const float* Wev1   = (const float*)d_in[18];
    const float* bev1   = (const float*)d_in[19];
    const float* tau1   = (const float*)d_in[20];
    const float* gamma1 = (const float*)d_in[21];
    const float* beta1  = (const float*)d_in[22];
    const float* Wskip  = (const float*)d_in[23];
    const float* bskip  = (const float*)d_in[24];
    const float* Wout   = (const float*)d_in[25];
    const float* bout   = (const float*)d_in[26];

    float* out = (float*)d_out;
    float* ew0 = out + BATCH;
    float* ew1 = ew0 + (size_t)BATCH * TT;

    const int TOT = 6 * H * H + INP * H;
    transpose_kernel<<<(TOT + 255) / 256, 256>>>(Wattn0, Wattn1, Wrec0, Wrec1,
                                                 Win1, Wskip, Win0);
    ew0_kernel<<<(BATCH * TT + 255) / 256, 256>>>(x, Wev0, bev0, ew0);

    liquid_kernel<<<GRID, NT>>>(
        x, bin0, brec0, battn0, tau0, gamma0, beta0,
        bin1, brec1, battn1, Wev1, bev1, tau1, gamma1, beta1,
        bskip, Wout, bout,
        out, ew0, ew1);
}

// round 5
// speedup vs baseline: 1.0994x; 1.0994x over previous
#include <cuda_runtime.h>
#include <math.h>

#define BATCH 512
#define TT    2048
#define INP   32
#define H     256
#define DTC   0.1f
#define EPSC  1e-5f
#define BB    4
#define GRID  (BATCH / BB)   /* 128 blocks */
#define NT    512            /* 2 layer-groups x 256 */

// Transposed-interleaved weight scratch: layout [k/4][j][k&3] per matrix.
// Order: Wattn0, Wattn1, Wrec0, Wrec1, Win1, Wskip, Win0
#define WOFF_A0 0
#define WOFF_A1 (1 * H * H)
#define WOFF_R0 (2 * H * H)
#define WOFF_R1 (3 * H * H)
#define WOFF_I1 (4 * H * H)
#define WOFF_SK (5 * H * H)
#define WOFF_I0 (6 * H * H)
__device__ __align__(16) float g_Wt[6 * H * H + INP * H];

__device__ __forceinline__ float sigmoidf_(float v) {
    return 1.0f / (1.0f + expf(-v));
}

// ---- packed f32x2 helpers ------------------------------------------------
__device__ __forceinline__ unsigned long long dup2(float w) {
    unsigned long long d;
    asm("mov.b64 %0, {%1, %1};" : "=l"(d) : "f"(w));
    return d;
}
__device__ __forceinline__ void ffma2(unsigned long long& d,
                                      unsigned long long a,
                                      unsigned long long b) {
    asm("fma.rn.f32x2 %0, %1, %2, %0;" : "+l"(d) : "l"(a), "l"(b));
}
__device__ __forceinline__ float2 unpk(unsigned long long v) {
    float2 r;
    asm("mov.b64 {%0, %1}, %2;" : "=f"(r.x), "=f"(r.y) : "l"(v));
    return r;
}

// Group-scoped named barrier (256 threads of one layer-group).
__device__ __forceinline__ void barx(int id) {
    asm volatile("bar.sync %0, %1;" :: "r"(id), "r"(256) : "memory");
}

// Group-local reduction over 8 warps of NV per-thread values -> stat[0..NV-1].
template <int NV>
__device__ __forceinline__ void group_reduce(float* vals, int barid, int gt,
                                             float (*red)[16], float* stat) {
    #pragma unroll
    for (int o = 16; o > 0; o >>= 1) {
        #pragma unroll
        for (int i = 0; i < NV; i++)
            vals[i] += __shfl_xor_sync(0xffffffffu, vals[i], o);
    }
    int w = gt >> 5, l = gt & 31;
    if (l == 0) {
        #pragma unroll
        for (int i = 0; i < NV; i++) red[w][i] = vals[i];
    }
    barx(barid);
    if (gt < NV) {
        float a = 0.f;
        #pragma unroll
        for (int w2 = 0; w2 < 8; w2++) a += red[w2][gt];
        stat[gt] = a;
    }
    barx(barid);
}

// [4 rows, 4*N4 k] x column j. Weights from transposed scratch (LDG.128,
// double-buffered), h from SMEM broadcast LDS.128. Sequential k into 2 accs
// (matches round-2 summation order for numerics).
template <int N4>
__device__ __forceinline__ void gemm_col(const float4* __restrict__ wp,
                                         const ulonglong2* __restrict__ hA,
                                         unsigned long long* acc) {
    float4 w0 = __ldg(wp);
    #pragma unroll 4
    for (int c = 0; c < N4; c++) {
        float4 wc = w0;
        if (c + 1 < N4) w0 = __ldg(wp + (c + 1) * H);
        ulonglong2 h0 = hA[4 * c + 0], h1 = hA[4 * c + 1];
        ulonglong2 h2 = hA[4 * c + 2], h3 = hA[4 * c + 3];
        unsigned long long w;
        w = dup2(wc.x); ffma2(acc[0], h0.x, w); ffma2(acc[1], h0.y, w);
        w = dup2(wc.y); ffma2(acc[0], h1.x, w); ffma2(acc[1], h1.y, w);
        w = dup2(wc.z); ffma2(acc[0], h2.x, w); ffma2(acc[1], h2.y, w);
        w = dup2(wc.w); ffma2(acc[0], h3.x, w); ffma2(acc[1], h3.y, w);
    }
}

__device__ __forceinline__ void acc_final(const unsigned long long* acc, float* r) {
    float2 lo = unpk(acc[0]), hi = unpk(acc[1]);
    r[0] = lo.x; r[1] = lo.y; r[2] = hi.x; r[3] = hi.y;
}

// ---------------------------------------------------------------------------
// Kernel 0: transpose weights into [k/4][j][k&3] interleaved layout.
// ---------------------------------------------------------------------------
__global__ void transpose_kernel(
    const float* __restrict__ A0, const float* __restrict__ A1,
    const float* __restrict__ R0, const float* __restrict__ R1,
    const float* __restrict__ I1, const float* __restrict__ SK,
    const float* __restrict__ I0)
{
    int idx = blockIdx.x * blockDim.x + threadIdx.x;
    const int BIG = 6 * H * H;
    if (idx < BIG) {
        int m = idx >> 16, rem = idx & 65535;
        int k = rem >> 8, j = rem & 255;
        const float* src = (m == 0) ? A0 : (m == 1) ? A1 : (m == 2) ? R0
                         : (m == 3) ? R1 : (m == 4) ? I1 : SK;
        g_Wt[(m << 16) + (k >> 2) * (H * 4) + j * 4 + (k & 3)] = src[rem];
    } else if (idx < BIG + INP * H) {
        int rem = idx - BIG;
        int k = rem >> 8, j = rem & 255;
        g_Wt[BIG + (k >> 2) * (H * 4) + j * 4 + (k & 3)] = I0[rem];
    }
}

// ---------------------------------------------------------------------------
// Kernel 1: ew0[b,t] = mask * sigmoid([x_t, x_{t-1}] @ Wev0 + bev0)
// ---------------------------------------------------------------------------
__global__ void ew0_kernel(const float* __restrict__ x,
                           const float* __restrict__ Wev0,
                           const float* __restrict__ bev0,
                           float* __restrict__ ew0_out) {
    int idx = blockIdx.x * blockDim.x + threadIdx.x;
    if (idx >= BATCH * TT) return;
    int t = idx & (TT - 1);
    float r = 0.f;
    if (t > 0) {
        const float* xc = x + (size_t)idx * INP;
        const float* xp = xc - INP;
        float s = bev0[0];
        #pragma unroll
        for (int i = 0; i < INP; i++) s += xc[i] * Wev0[i];
        #pragma unroll
        for (int i = 0; i < INP; i++) s += xp[i] * Wev0[INP + i];
        r = sigmoidf_(s);
    }
    ew0_out[idx] = r;
}

// ---------------------------------------------------------------------------
// Kernel 2: persistent recurrence. 512 threads = 2 layer-groups x 256 units.
// g0 (warps 0-7):  attn0, in0, rec0, cell0+LN0, ew1, skip   (layer 0)
// g1 (warps 8-15): attn1, rec1, in1, cell1+LN1, out         (layer 1)
// Only 2 full barriers/step; everything else group-scoped bar.sync.
// ---------------------------------------------------------------------------
__global__ __launch_bounds__(NT, 1) void liquid_kernel(
    const float* __restrict__ x,
    const float* __restrict__ bin0,  const float* __restrict__ brec0,
    const float* __restrict__ battn0,
    const float* __restrict__ tau0,  const float* __restrict__ gamma0, const float* __restrict__ beta0,
    const float* __restrict__ bin1,  const float* __restrict__ brec1,
    const float* __restrict__ battn1,
    const float* __restrict__ Wev1,  const float* __restrict__ bev1,
    const float* __restrict__ tau1,  const float* __restrict__ gamma1, const float* __restrict__ beta1,
    const float* __restrict__ bskip,
    const float* __restrict__ Wout,  const float* __restrict__ bout,
    float* __restrict__ out,
    const float* __restrict__ ew0_all,
    float* __restrict__ ew1_all)
{
    __shared__ __align__(16) float h0p[2][H][4];   // layer-0 hidden (ping-pong), g0-written
    __shared__ __align__(16) float h1p[2][H][4];   // layer-1 hidden (ping-pong), g1-private
    __shared__ __align__(16) float ha0p[H][4];     // h0*attn0, g0-private
    __shared__ __align__(16) float ha1p[H][4];     // h1*attn1, g1-private
    __shared__ __align__(16) float skp[H][4];      // h0n@Wskip+bskip (g0 -> g1)
    __shared__ __align__(16) float xp[INP][4];     // x_t staging (g0-private)
    __shared__ float red0[8][16], red1[8][16];
    __shared__ float stat0[16], stat1[16];
    __shared__ float ew1_s[BB];

    const int tid  = threadIdx.x;
    const int g    = tid >> 8;        // layer-group
    const int j    = tid & 255;       // hidden unit / group-local tid
    const int row0 = blockIdx.x * BB;
    const int barid = 1 + g;
    float (*red)[16] = g ? red1 : red0;
    float* stat      = g ? stat1 : stat0;

    // ---- per-group constants ----
    float c_battn, c_brec, it, c_g, c_b;
    float c_bin0 = 0.f, c_bin1 = 0.f, wv1a = 0.f, wv1b = 0.f, c_bev1 = 0.f;
    float c_bskip = 0.f, c_wout = 0.f;
    if (g == 0) {
        c_battn = battn0[j]; c_brec = brec0[j];
        it = DTC / fminf(fmaxf(tau0[j], 0.1f), 10.0f);
        c_g = gamma0[j]; c_b = beta0[j];
        c_bin0 = bin0[j]; c_bskip = bskip[j];
        wv1a = Wev1[j]; wv1b = Wev1[H + j]; c_bev1 = bev1[0];
    } else {
        c_battn = battn1[j]; c_brec = brec1[j];
        it = DTC / fminf(fmaxf(tau1[j], 0.1f), 10.0f);
        c_g = gamma1[j]; c_b = beta1[j];
        c_bin1 = bin1[j]; c_wout = Wout[j];
    }
    const float gw = c_g * wv1a;   // g0 only

    // Fold-constants for ew1 logit (g0-local reduction)
    float C2 = 0.f, C3 = 0.f;
    if (g == 0) {
        float cc[2] = { gw, c_b * wv1a };
        group_reduce<2>(cc, barid, j, red, stat);
        C2 = stat[0]; C3 = stat[1];
    }

    // Weight bases (transposed layout), offset by unit j
    const float4* wB = (const float4*)(g_Wt + (g ? WOFF_A1 : WOFF_A0)) + j;
    const float4* wC = (const float4*)(g_Wt + (g ? WOFF_R1 : WOFF_R0)) + j;
    const float4* wE = (const float4*)(g_Wt + (g ? WOFF_I1 : WOFF_SK)) + j;
    const float4* wI = (const float4*)(g_Wt + WOFF_I0) + j;

    float hown[BB] = {0.f, 0.f, 0.f, 0.f};   // g0: h0 rows; g1: h1 rows
    if (g == 0) *(float4*)&h0p[0][j][0] = make_float4(0.f, 0.f, 0.f, 0.f);
    else        *(float4*)&h1p[0][j][0] = make_float4(0.f, 0.f, 0.f, 0.f);
    __syncthreads();

    for (int t = 0; t < TT; t++) {
        const int cur = t & 1, nxt = cur ^ 1;

        if (g == 0) {
            // ---- A: per-row ew0 + x_t staging (g0-private) ----
            float e0r[BB];
            #pragma unroll
            for (int r = 0; r < BB; r++)
                e0r[r] = ew0_all[(size_t)(row0 + r) * TT + t];
            if (j < INP) {
                float4 xv;
                xv.x = x[((size_t)(row0 + 0) * TT + t) * INP + j];
                xv.y = x[((size_t)(row0 + 1) * TT + t) * INP + j];
                xv.z = x[((size_t)(row0 + 2) * TT + t) * INP + j];
                xv.w = x[((size_t)(row0 + 3) * TT + t) * INP + j];
                *(float4*)&xp[j][0] = xv;
            }
            barx(1);

            // ---- B: attn0 + in0 ----
            unsigned long long acc[2];
            acc[0] = acc[1] = dup2(c_battn);
            gemm_col<H / 4>(wB, (const ulonglong2*)&h0p[cur][0][0], acc);
            float av[4]; acc_final(acc, av);

            unsigned long long ia[2];
            ia[0] = ia[1] = dup2(c_bin0);
            gemm_col<INP / 4>(wI, (const ulonglong2*)&xp[0][0], ia);
            float iv[4]; acc_final(ia, iv);
            float i0t[BB];
            #pragma unroll
            for (int r = 0; r < BB; r++) i0t[r] = tanhf(iv[r]);

            *(float4*)&ha0p[j][0] = make_float4(
                hown[0] * sigmoidf_(av[0]), hown[1] * sigmoidf_(av[1]),
                hown[2] * sigmoidf_(av[2]), hown[3] * sigmoidf_(av[3]));
            barx(1);

            // ---- C: rec0 ----
            unsigned long long rc[2];
            rc[0] = rc[1] = dup2(c_brec);
            gemm_col<H / 4>(wC, (const ulonglong2*)&ha0p[0][0], rc);
            float rv[4]; acc_final(rc, rv);

            // ---- D: cell0 + LN0 + folded ew1 logit (group-local reduce) ----
            float v0[BB], vals[16];
            #pragma unroll
            for (int r = 0; r < BB; r++) {
                float h = hown[r];
                v0[r] = h + it * (-h + i0t[r] + tanhf(rv[r])) * (1.f + e0r[r]);
                vals[4 * r + 0] = v0[r];
                vals[4 * r + 1] = v0[r] * v0[r];
                vals[4 * r + 2] = v0[r] * gw;
                vals[4 * r + 3] = h * wv1b;
            }
            group_reduce<16>(vals, 1, j, red, stat);

            float h0n[BB];
            #pragma unroll
            for (int r = 0; r < BB; r++) {
                float mu  = stat[4 * r] * (1.f / H);
                float var = stat[4 * r + 1] * (1.f / H) - mu * mu;
                h0n[r] = (v0[r] - mu) * rsqrtf(var + EPSC) * c_g + c_b;
            }
            *(float4*)&h0p[nxt][j][0] = make_float4(h0n[0], h0n[1], h0n[2], h0n[3]);
            if (j < BB) {
                int r = j;
                float mu  = stat[4 * r] * (1.f / H);
                float var = stat[4 * r + 1] * (1.f / H) - mu * mu;
                float rs  = rsqrtf(var + EPSC);
                float lg  = rs * (stat[4 * r + 2] - mu * C2) + C3 + stat[4 * r + 3] + c_bev1;
                float e   = (t > 0) ? sigmoidf_(lg) : 0.f;
                ew1_s[r]  = e;
                ew1_all[(size_t)(row0 + r) * TT + t] = e;
            }
            __syncthreads();   // FULL1: h0p[nxt] + ew1_s -> g1

            // ---- E: skip = h0n @ Wskip + bskip ----
            unsigned long long sa[2];
            sa[0] = sa[1] = dup2(c_bskip);
            gemm_col<H / 4>(wE, (const ulonglong2*)&h0p[nxt][0][0], sa);
            float sv[4]; acc_final(sa, sv);
            *(float4*)&skp[j][0] = make_float4(sv[0], sv[1], sv[2], sv[3]);
            __syncthreads();   // FULL2: skp -> g1

            #pragma unroll
            for (int r = 0; r < BB; r++) hown[r] = h0n[r];
        } else {
            // ---- B: attn1 ----
            barx(2);           // orders prev-step h1p[nxt] write -> read
            unsigned long long acc[2];
            acc[0] = acc[1] = dup2(c_battn);
            gemm_col<H / 4>(wB, (const ulonglong2*)&h1p[cur][0][0], acc);
            float av[4]; acc_final(acc, av);
            *(float4*)&ha1p[j][0] = make_float4(
                hown[0] * sigmoidf_(av[0]), hown[1] * sigmoidf_(av[1]),
                hown[2] * sigmoidf_(av[2]), hown[3] * sigmoidf_(av[3]));
            barx(2);

            // ---- C: rec1 ----
            unsigned long long rc[2];
            rc[0] = rc[1] = dup2(c_brec);
            gemm_col<H / 4>(wC, (const ulonglong2*)&ha1p[0][0], rc);
            float rv[4]; acc_final(rc, rv);
            float t_rc1[BB];
            #pragma unroll
            for (int r = 0; r < BB; r++) t_rc1[r] = tanhf(rv[r]);

            __syncthreads();   // FULL1: wait for h0p[nxt] + ew1_s

            // ---- E: in1 = tanh(h0n @ Win1 + bin1) (registers only) ----
            unsigned long long ia[2];
            ia[0] = ia[1] = dup2(c_bin1);
            gemm_col<H / 4>(wE, (const ulonglong2*)&h0p[nxt][0][0], ia);
            float iv[4]; acc_final(ia, iv);
            float i1t[BB];
            #pragma unroll
            for (int r = 0; r < BB; r++) i1t[r] = tanhf(iv[r]);

            __syncthreads();   // FULL2: wait for skp

            // ---- F: cell1 + LN1 + skip (group-local reduce) ----
            float4 sk4 = *(const float4*)&skp[j][0];
            float skv[4] = { sk4.x, sk4.y, sk4.z, sk4.w };
            float v1[BB], vf[8];
            #pragma unroll
            for (int r = 0; r < BB; r++) {
                float h = hown[r];
                v1[r] = h + it * (-h + i1t[r] + t_rc1[r]) * (1.f + ew1_s[r]);
                vf[2 * r]     = v1[r];
                vf[2 * r + 1] = v1[r] * v1[r];
            }
            group_reduce<8>(vf, 2, j, red, stat);
            #pragma unroll
            for (int r = 0; r < BB; r++) {
                float mu  = stat[2 * r] * (1.f / H);
                float var = stat[2 * r + 1] * (1.f / H) - mu * mu;
                hown[r] = (v1[r] - mu) * rsqrtf(var + EPSC) * c_g + c_b + skv[r];
            }
            *(float4*)&h1p[nxt][j][0] = make_float4(hown[0], hown[1], hown[2], hown[3]);
            // next step's barx(2) orders these writes
        }
    }

    // ---- Final readout: out[b] = h1 @ Wout + bout (g1 only) ----
    __syncthreads();
    if (g == 1) {
        float oc[BB];
        #pragma unroll
        for (int r = 0; r < BB; r++) oc[r] = hown[r] * c_wout;
        group_reduce<4>(oc, 2, j, red, stat);
        if (j < BB) out[row0 + j] = stat[j] + bout[0];
    }
}

extern "C" void kernel_launch(void* const* d_in, const int* in_sizes, int n_in,
                              void* d_out, int out_size) {
    const float* x      = (const float*)d_in[0];
    const float* Win0   = (const float*)d_in[1];
    const float* bin0   = (const float*)d_in[2];
    const float* Wrec0  = (const float*)d_in[3];
    const float* brec0  = (const float*)d_in[4];
    const float* Wattn0 = (const float*)d_in[5];
    const float* battn0 = (const float*)d_in[6];
    const float* Wev0   = (const float*)d_in[7];
    const float* bev0   = (const float*)d_in[8];
    const float* tau0   = (const float*)d_in[9];
    const float* gamma0 = (const float*)d_in[10];
    const float* beta0  = (const float*)d_in[11];
    const float* Win1   = (const float*)d_in[12];
    const float* bin1   = (const float*)d_in[13];
    const float* Wrec1  = (const float*)d_in[14];
    const float* brec1  = (const float*)d_in[15];
    const float* Wattn1 = (const float*)d_in[16];
    const float* battn1 = (const float*)d_in[17];
    const float* Wev1   = (const float*)d_in[18];
    const float* bev1   = (const float*)d_in[19];
    const float* tau1   = (const float*)d_in[20];
    const float* gamma1 = (const float*)d_in[21];
    const float* beta1  = (const float*)d_in[22];
    const float* Wskip  = (const float*)d_in[23];
    const float* bskip  = (const float*)d_in[24];
    const float* Wout   = (const float*)d_in[25];
    const float* bout   = (const float*)d_in[26];

    float* out = (float*)d_out;
    float* ew0 = out + BATCH;
    float* ew1 = ew0 + (size_t)BATCH * TT;

    const int TOT = 6 * H * H + INP * H;
    transpose_kernel<<<(TOT + 255) / 256, 256>>>(Wattn0, Wattn1, Wrec0, Wrec1,
                                                 Win1, Wskip, Win0);
    ew0_kernel<<<(BATCH * TT + 255) / 256, 256>>>(x, Wev0, bev0, ew0);

    liquid_kernel<<<GRID, NT>>>(
        x, bin0, brec0, battn0, tau0, gamma0, beta0,
        bin1, brec1, battn1, Wev1, bev1, tau1, gamma1, beta1,
        bskip, Wout, bout,
        out, ew0, ew1);
}

// round 7
// speedup vs baseline: 1.3489x; 1.2269x over previous
#include <cuda_runtime.h>
#include <math.h>

#define BATCH 512
#define TT    2048
#define INP   32
#define H     256
#define DTC   0.1f
#define EPSC  1e-5f
#define BB    4
#define GRID  (BATCH / BB)   /* 128 blocks */
#define NT    512            /* 2 layer-groups x 256 */

typedef unsigned long long ull;

// Transposed-interleaved weight scratch: layout [k/4][j][k&3] per matrix.
#define WOFF_A0 0
#define WOFF_A1 (1 * H * H)
#define WOFF_R0 (2 * H * H)
#define WOFF_R1 (3 * H * H)
#define WOFF_I1 (4 * H * H)
#define WOFF_SK (5 * H * H)
#define WOFF_I0 (6 * H * H)
__device__ __align__(16) float g_Wt[6 * H * H + INP * H];

// Dynamic smem layout (bytes)
#define SM_CMB0  0        /* 256*3*16 = 12288 */
#define SM_CMB1  12288    /* 12288 */
#define SM_H0Q   24576    /* 2 * 4096 */
#define SM_H1Q   32768    /* 2 * 4096 */
#define SM_HA0   40960    /* 4096 */
#define SM_HA1   45056    /* 4096 */
#define SM_SKP   49152    /* 4096 */
#define SM_XQ    53248    /* 512 */
#define SM_RED0  53760    /* 512 */
#define SM_RED1  54272    /* 512 */
#define SM_STAT0 54784    /* 64 */
#define SM_STAT1 54848    /* 64 */
#define SM_EW1   54912    /* 16 */
#define SMEM_BYTES 55296

__device__ __forceinline__ float sigmoidf_(float v) {
    return 1.0f / (1.0f + expf(-v));
}
__device__ __forceinline__ void ffma2(ull& d, ull a, ull b) {
    asm("fma.rn.f32x2 %0, %1, %2, %0;" : "+l"(d) : "l"(a), "l"(b));
}
__device__ __forceinline__ ull fadd2(ull a, ull b) {
    ull r; asm("add.rn.f32x2 %0, %1, %2;" : "=l"(r) : "l"(a), "l"(b)); return r;
}
__device__ __forceinline__ float hadd2(ull a) {
    float lo, hi; asm("mov.b64 {%0, %1}, %2;" : "=f"(lo), "=f"(hi) : "l"(a));
    return lo + hi;
}
__device__ __forceinline__ void barx(int id) {
    asm volatile("bar.sync %0, %1;" :: "r"(id), "r"(256) : "memory");
}

// Group-local reduction over 8 warps of NV values -> stat[0..NV-1].
template <int NV>
__device__ __forceinline__ void group_reduce(float* vals, int barid, int gt,
                                             float (*red)[16], float* stat) {
    #pragma unroll
    for (int o = 16; o > 0; o >>= 1) {
        #pragma unroll
        for (int i = 0; i < NV; i++)
            vals[i] += __shfl_xor_sync(0xffffffffu, vals[i], o);
    }
    int w = gt >> 5, l = gt & 31;
    if (l == 0) {
        #pragma unroll
        for (int i = 0; i < NV; i++) red[w][i] = vals[i];
    }
    barx(barid);
    if (gt < NV) {
        float a = 0.f;
        #pragma unroll
        for (int w2 = 0; w2 < 8; w2++) a += red[w2][gt];
        stat[gt] = a;
    }
    barx(barid);
}

// Write unit-j row values v[0..3] into pair-interleaved layout:
// buf[p*8 + {0..3}] = (h_2p[0], h_2p+1[0], h_2p[1], h_2p+1[1]); +4 = rows 2,3.
__device__ __forceinline__ void writePair(float* buf, int j, const float* v) {
    float o0 = __shfl_xor_sync(0xffffffffu, v[0], 1);
    float o1 = __shfl_xor_sync(0xffffffffu, v[1], 1);
    float o2 = __shfl_xor_sync(0xffffffffu, v[2], 1);
    float o3 = __shfl_xor_sync(0xffffffffu, v[3], 1);
    int p = j >> 1;
    if ((j & 1) == 0) *(float4*)(buf + p * 8)     = make_float4(v[0], o0, v[1], o1);
    else              *(float4*)(buf + p * 8 + 4) = make_float4(o2, v[2], o3, v[3]);
}

// Dual-column GEMM over NCH 4-k chunks. Weights packed (w_k,w_k+1) pairs from
// scratch (coalesced LDG.128, double-buffered); h from pair-layout smem.
// acc[r] = f32x2 (even-k partial, odd-k partial) for row r.
template <int NCH, bool DUAL>
__device__ __forceinline__ void gemm2(const ulonglong2* __restrict__ wX,
                                      const ulonglong2* __restrict__ wY,
                                      const ulonglong2* __restrict__ hq,
                                      ull* aX, ull* aY) {
    ulonglong2 wx = __ldg(wX), wy;
    if (DUAL) wy = __ldg(wY);
    #pragma unroll 4
    for (int i = 0; i < NCH; i++) {
        ulonglong2 cwx = wx, cwy;
        if (DUAL) cwy = wy;
        if (i + 1 < NCH) {
            wx = __ldg(wX + (i + 1) * 256);
            if (DUAL) wy = __ldg(wY + (i + 1) * 256);
        }
        ulonglong2 h0 = hq[4 * i], h1 = hq[4 * i + 1];
        ulonglong2 h2 = hq[4 * i + 2], h3 = hq[4 * i + 3];
        ffma2(aX[0], h0.x, cwx.x); ffma2(aX[1], h0.y, cwx.x);
        ffma2(aX[2], h1.x, cwx.x); ffma2(aX[3], h1.y, cwx.x);
        ffma2(aX[0], h2.x, cwx.y); ffma2(aX[1], h2.y, cwx.y);
        ffma2(aX[2], h3.x, cwx.y); ffma2(aX[3], h3.y, cwx.y);
        if (DUAL) {
            ffma2(aY[0], h0.x, cwy.x); ffma2(aY[1], h0.y, cwy.x);
            ffma2(aY[2], h1.x, cwy.x); ffma2(aY[3], h1.y, cwy.x);
            ffma2(aY[0], h2.x, cwy.y); ffma2(aY[1], h2.y, cwy.y);
            ffma2(aY[2], h3.x, cwy.y); ffma2(aY[3], h3.y, cwy.y);
        }
    }
}

// Exchange colY partials with partner j^128, return full col-j sums (4 rows).
__device__ __forceinline__ void combine4(ulonglong2* cmbg, int j, int barid,
                                         const ull* aX, const ull* aY, float* res) {
    ulonglong2* slot = cmbg + (j ^ 128) * 3;
    ulonglong2 w0, w1;
    w0.x = aY[0]; w0.y = aY[1]; w1.x = aY[2]; w1.y = aY[3];
    slot[0] = w0; slot[1] = w1;
    barx(barid);
    const ulonglong2* my = cmbg + j * 3;
    ulonglong2 p0 = my[0], p1 = my[1];
    res[0] = hadd2(fadd2(aX[0], p0.x));
    res[1] = hadd2(fadd2(aX[1], p0.y));
    res[2] = hadd2(fadd2(aX[2], p1.x));
    res[3] = hadd2(fadd2(aX[3], p1.y));
}

// ---------------------------------------------------------------------------
// Kernel 0: transpose weights into [k/4][j][k&3] interleaved layout.
// ---------------------------------------------------------------------------
__global__ void transpose_kernel(
    const float* __restrict__ A0, const float* __restrict__ A1,
    const float* __restrict__ R0, const float* __restrict__ R1,
    const float* __restrict__ I1, const float* __restrict__ SK,
    const float* __restrict__ I0)
{
    int idx = blockIdx.x * blockDim.x + threadIdx.x;
    const int BIG = 6 * H * H;
    if (idx < BIG) {
        int m = idx >> 16, rem = idx & 65535;
        int k = rem >> 8, j = rem & 255;
        const float* src = (m == 0) ? A0 : (m == 1) ? A1 : (m == 2) ? R0
                         : (m == 3) ? R1 : (m == 4) ? I1 : SK;
        g_Wt[(m << 16) + (k >> 2) * (H * 4) + j * 4 + (k & 3)] = src[rem];
    } else if (idx < BIG + INP * H) {
        int rem = idx - BIG;
        int k = rem >> 8, j = rem & 255;
        g_Wt[BIG + (k >> 2) * (H * 4) + j * 4 + (k & 3)] = I0[rem];
    }
}

// ---------------------------------------------------------------------------
// Kernel 1: ew0[b,t] = mask * sigmoid([x_t, x_{t-1}] @ Wev0 + bev0)
// ---------------------------------------------------------------------------
__global__ void ew0_kernel(const float* __restrict__ x,
                           const float* __restrict__ Wev0,
                           const float* __restrict__ bev0,
                           float* __restrict__ ew0_out) {
    int idx = blockIdx.x * blockDim.x + threadIdx.x;
    if (idx >= BATCH * TT) return;
    int t = idx & (TT - 1);
    float r = 0.f;
    if (t > 0) {
        const float* xc = x + (size_t)idx * INP;
        const float* xp = xc - INP;
        float s = bev0[0];
        #pragma unroll
        for (int i = 0; i < INP; i++) s += xc[i] * Wev0[i];
        #pragma unroll
        for (int i = 0; i < INP; i++) s += xp[i] * Wev0[INP + i];
        r = sigmoidf_(s);
    }
    ew0_out[idx] = r;
}

// ---------------------------------------------------------------------------
// Kernel 2: persistent recurrence. 512 threads = 2 layer-groups x 256.
// Thread j computes cols {j, j^128} over k-half (j>>7); partner has the other
// half; partials exchanged through smem. Group0 = layer0, group1 = layer1.
// ---------------------------------------------------------------------------
__global__ __launch_bounds__(NT, 1) void liquid_kernel(
    const float* __restrict__ x,
    const float* __restrict__ bin0,  const float* __restrict__ brec0,
    const float* __restrict__ battn0,
    const float* __restrict__ tau0,  const float* __restrict__ gamma0, const float* __restrict__ beta0,
    const float* __restrict__ bin1,  const float* __restrict__ brec1,
    const float* __restrict__ battn1,
    const float* __restrict__ Wev1,  const float* __restrict__ bev1,
    const float* __restrict__ tau1,  const float* __restrict__ gamma1, const float* __restrict__ beta1,
    const float* __restrict__ bskip,
    const float* __restrict__ Wout,  const float* __restrict__ bout,
    float* __restrict__ out,
    const float* __restrict__ ew0_all,
    float* __restrict__ ew1_all)
{
    extern __shared__ __align__(16) char smraw[];

    const int tid  = threadIdx.x;
    const int g    = tid >> 8;        // layer-group
    const int j    = tid & 255;       // unit / group-local tid
    const int s    = j >> 7;          // k-half
    const int row0 = blockIdx.x * BB;
    const int barid = 1 + g;

    ulonglong2* cmb  = (ulonglong2*)(smraw + (g ? SM_CMB1 : SM_CMB0));
    float* h0q0 = (float*)(smraw + SM_H0Q);
    float* h0q1 = (float*)(smraw + SM_H0Q + 4096);
    float* h1q0 = (float*)(smraw + SM_H1Q);
    float* h1q1 = (float*)(smraw + SM_H1Q + 4096);
    float* ha0q = (float*)(smraw + SM_HA0);
    float* ha1q = (float*)(smraw + SM_HA1);
    float* skp  = (float*)(smraw + SM_SKP);
    float* xq   = (float*)(smraw + SM_XQ);
    float (*red)[16] = (float (*)[16])(smraw + (g ? SM_RED1 : SM_RED0));
    float* stat      = (float*)(smraw + (g ? SM_STAT1 : SM_STAT0));
    float* ew1_s     = (float*)(smraw + SM_EW1);

    // ---- per-group constants ----
    float c_battn, c_brec, it, c_g, c_b;
    float c_bin0 = 0.f, c_bin1 = 0.f, wv1a = 0.f, wv1b = 0.f, c_bev1 = 0.f;
    float c_bskip = 0.f, c_wout = 0.f;
    if (g == 0) {
        c_battn = battn0[j]; c_brec = brec0[j];
        it = DTC / fminf(fmaxf(tau0[j], 0.1f), 10.0f);
        c_g = gamma0[j]; c_b = beta0[j];
        c_bin0 = bin0[j]; c_bskip = bskip[j];
        wv1a = Wev1[j]; wv1b = Wev1[H + j]; c_bev1 = bev1[0];
    } else {
        c_battn = battn1[j]; c_brec = brec1[j];
        it = DTC / fminf(fmaxf(tau1[j], 0.1f), 10.0f);
        c_g = gamma1[j]; c_b = beta1[j];
        c_bin1 = bin1[j]; c_wout = Wout[j];
    }
    const float gw = c_g * wv1a;

    float C2 = 0.f, C3 = 0.f;
    if (g == 0) {
        float cc[2] = { gw, c_b * wv1a };
        group_reduce<2>(cc, barid, j, red, stat);
        C2 = stat[0]; C3 = stat[1];
    }

    // Weight bases: matrix base + k-half offset + column (ulonglong2 units).
    const int so = s * 32 * 256;
    const ulonglong2* WB = (const ulonglong2*)(g_Wt + (g ? WOFF_A1 : WOFF_A0)) + so;
    const ulonglong2* WC = (const ulonglong2*)(g_Wt + (g ? WOFF_R1 : WOFF_R0)) + so;
    const ulonglong2* WE = (const ulonglong2*)(g_Wt + (g ? WOFF_I1 : WOFF_SK)) + so;
    const ulonglong2* WI = (const ulonglong2*)(g_Wt + WOFF_I0) + j;
    const int jx = j ^ 128;

    float hown[BB] = {0.f, 0.f, 0.f, 0.f};
    if (g == 0) *(float4*)(h0q0 + j * 4) = make_float4(0.f, 0.f, 0.f, 0.f);
    else        *(float4*)(h1q0 + j * 4) = make_float4(0.f, 0.f, 0.f, 0.f);
    __syncthreads();

    for (int t = 0; t < TT; t++) {
        float* hqcur = (t & 1) ? ((g == 0) ? h0q1 : h1q1) : ((g == 0) ? h0q0 : h1q0);
        float* h0nxt = (t & 1) ? h0q0 : h0q1;
        float* h1nxt = (t & 1) ? h1q0 : h1q1;

        if (g == 0) {
            // ---- A: ew0 + x_t staging ----
            float e0r[BB];
            #pragma unroll
            for (int r = 0; r < BB; r++)
                e0r[r] = ew0_all[(size_t)(row0 + r) * TT + t];
            if (j < INP) {
                float xv[4];
                xv[0] = x[((size_t)(row0 + 0) * TT + t) * INP + j];
                xv[1] = x[((size_t)(row0 + 1) * TT + t) * INP + j];
                xv[2] = x[((size_t)(row0 + 2) * TT + t) * INP + j];
                xv[3] = x[((size_t)(row0 + 3) * TT + t) * INP + j];
                writePair(xq, j, xv);
            }
            barx(1);

            // ---- B: attn0 (split) + in0 (full, own col) ----
            ull aX[4] = {0,0,0,0}, aY[4] = {0,0,0,0}, ia[4] = {0,0,0,0};
            gemm2<32, true>(WB + j, WB + jx,
                            (const ulonglong2*)hqcur + s * 128, aX, aY);
            gemm2<8, false>(WI, WI, (const ulonglong2*)xq, ia, ia);
            float av[4];
            combine4(cmb, j, 1, aX, aY, av);
            float i0t[BB], hv[4];
            #pragma unroll
            for (int r = 0; r < BB; r++) {
                i0t[r] = tanhf(hadd2(ia[r]) + c_bin0);
                hv[r]  = hown[r] * sigmoidf_(av[r] + c_battn);
            }
            writePair(ha0q, j, hv);
            barx(1);

            // ---- C: rec0 ----
            ull rX[4] = {0,0,0,0}, rY[4] = {0,0,0,0};
            gemm2<32, true>(WC + j, WC + jx,
                            (const ulonglong2*)ha0q + s * 128, rX, rY);
            float rv[4];
            combine4(cmb, j, 1, rX, rY, rv);

            // ---- D: cell0 + LN0 + folded ew1 logit ----
            float v0[BB], vals[16];
            #pragma unroll
            for (int r = 0; r < BB; r++) {
                float h = hown[r];
                v0[r] = h + it * (-h + i0t[r] + tanhf(rv[r] + c_brec)) * (1.f + e0r[r]);
                vals[4 * r + 0] = v0[r];
                vals[4 * r + 1] = v0[r] * v0[r];
                vals[4 * r + 2] = v0[r] * gw;
                vals[4 * r + 3] = h * wv1b;
            }
            group_reduce<16>(vals, 1, j, red, stat);

            float h0n[BB];
            #pragma unroll
            for (int r = 0; r < BB; r++) {
                float mu  = stat[4 * r] * (1.f / H);
                float var = stat[4 * r + 1] * (1.f / H) - mu * mu;
                h0n[r] = (v0[r] - mu) * rsqrtf(var + EPSC) * c_g + c_b;
            }
            writePair(h0nxt, j, h0n);
            if (j < BB) {
                int r = j;
                float mu  = stat[4 * r] * (1.f / H);
                float var = stat[4 * r + 1] * (1.f / H) - mu * mu;
                float rs  = rsqrtf(var + EPSC);
                float lg  = rs * (stat[4 * r + 2] - mu * C2) + C3 + stat[4 * r + 3] + c_bev1;
                float e   = (t > 0) ? sigmoidf_(lg) : 0.f;
                ew1_s[r]  = e;
                ew1_all[(size_t)(row0 + r) * TT + t] = e;
            }
            __syncthreads();   // FULL1: h0nxt + ew1_s -> g1

            // ---- E: skip ----
            ull sX[4] = {0,0,0,0}, sY[4] = {0,0,0,0};
            gemm2<32, true>(WE + j, WE + jx,
                            (const ulonglong2*)h0nxt + s * 128, sX, sY);
            float sv[4];
            combine4(cmb, j, 1, sX, sY, sv);
            *(float4*)(skp + j * 4) = make_float4(sv[0] + c_bskip, sv[1] + c_bskip,
                                                  sv[2] + c_bskip, sv[3] + c_bskip);
            __syncthreads();   // FULL2: skp -> g1

            #pragma unroll
            for (int r = 0; r < BB; r++) hown[r] = h0n[r];
        } else {
            // ---- B: attn1 ----
            barx(2);           // orders prev-step h1nxt write -> read
            ull aX[4] = {0,0,0,0}, aY[4] = {0,0,0,0};
            gemm2<32, true>(WB + j, WB + jx,
                            (const ulonglong2*)hqcur + s * 128, aX, aY);
            float av[4];
            combine4(cmb, j, 2, aX, aY, av);
            float hv[4];
            #pragma unroll
            for (int r = 0; r < BB; r++)
                hv[r] = hown[r] * sigmoidf_(av[r] + c_battn);
            writePair(ha1q, j, hv);
            barx(2);

            // ---- C: rec1 ----
            ull rX[4] = {0,0,0,0}, rY[4] = {0,0,0,0};
            gemm2<32, true>(WC + j, WC + jx,
                            (const ulonglong2*)ha1q + s * 128, rX, rY);
            float rv[4];
            combine4(cmb, j, 2, rX, rY, rv);
            float t_rc1[BB];
            #pragma unroll
            for (int r = 0; r < BB; r++) t_rc1[r] = tanhf(rv[r] + c_brec);

            __syncthreads();   // FULL1: wait h0nxt + ew1_s

            // ---- E: in1 ----
            ull iX[4] = {0,0,0,0}, iY[4] = {0,0,0,0};
            gemm2<32, true>(WE + j, WE + jx,
                            (const ulonglong2*)h0nxt + s * 128, iX, iY);
            float iv[4];
            combine4(cmb, j, 2, iX, iY, iv);
            float i1t[BB];
            #pragma unroll
            for (int r = 0; r < BB; r++) i1t[r] = tanhf(iv[r] + c_bin1);

            __syncthreads();   // FULL2: wait skp

            // ---- F: cell1 + LN1 + skip ----
            float4 sk4 = *(const float4*)(skp + j * 4);
            float skv[4] = { sk4.x, sk4.y, sk4.z, sk4.w };
            float ewl[4] = { ew1_s[0], ew1_s[1], ew1_s[2], ew1_s[3] };
            float v1[BB], vf[8];
            #pragma unroll
            for (int r = 0; r < BB; r++) {
                float h = hown[r];
                v1[r] = h + it * (-h + i1t[r] + t_rc1[r]) * (1.f + ewl[r]);
                vf[2 * r]     = v1[r];
                vf[2 * r + 1] = v1[r] * v1[r];
            }
            group_reduce<8>(vf, 2, j, red, stat);
            #pragma unroll
            for (int r = 0; r < BB; r++) {
                float mu  = stat[2 * r] * (1.f / H);
                float var = stat[2 * r + 1] * (1.f / H) - mu * mu;
                hown[r] = (v1[r] - mu) * rsqrtf(var + EPSC) * c_g + c_b + skv[r];
            }
            writePair(h1nxt, j, hown);
            // next step's barx(2) orders these writes
        }
    }

    // ---- Final readout: out[b] = h1 @ Wout + bout (g1) ----
    __syncthreads();
    if (g == 1) {
        float oc[BB];
        #pragma unroll
        for (int r = 0; r < BB; r++) oc[r] = hown[r] * c_wout;
        group_reduce<4>(oc, 2, j, red, stat);
        if (j < BB) out[row0 + j] = stat[j] + bout[0];
    }
}

extern "C" void kernel_launch(void* const* d_in, const int* in_sizes, int n_in,
                              void* d_out, int out_size) {
    const float* x      = (const float*)d_in[0];
    const float* Win0   = (const float*)d_in[1];
    const float* bin0   = (const float*)d_in[2];
    const float* Wrec0  = (const float*)d_in[3];
    const float* brec0  = (const float*)d_in[4];
    const float* Wattn0 = (const float*)d_in[5];
    const float* battn0 = (const float*)d_in[6];
    const float* Wev0   = (const float*)d_in[7];
    const float* bev0   = (const float*)d_in[8];
    const float* tau0   = (const float*)d_in[9];
    const float* gamma0 = (const float*)d_in[10];
    const float* beta0  = (const float*)d_in[11];
    const float* Win1   = (const float*)d_in[12];
    const float* bin1   = (const float*)d_in[13];
    const float* Wrec1  = (const float*)d_in[14];
    const float* brec1  = (const float*)d_in[15];
    const float* Wattn1 = (const float*)d_in[16];
    const float* battn1 = (const float*)d_in[17];
    const float* Wev1   = (const float*)d_in[18];
    const float* bev1   = (const float*)d_in[19];
    const float* tau1   = (const float*)d_in[20];
    const float* gamma1 = (const float*)d_in[21];
    const float* beta1  = (const float*)d_in[22];
    const float* Wskip  = (const float*)d_in[23];
    const float* bskip  = (const float*)d_in[24];
    const float* Wout   = (const float*)d_in[25];
    const float* bout   = (const float*)d_in[26];

    float* out = (float*)d_out;
    float* ew0 = out + BATCH;
    float* ew1 = ew0 + (size_t)BATCH * TT;

    const int TOT = 6 * H * H + INP * H;
    transpose_kernel<<<(TOT + 255) / 256, 256>>>(Wattn0, Wattn1, Wrec0, Wrec1,
                                                 Win1, Wskip, Win0);
    ew0_kernel<<<(BATCH * TT + 255) / 256, 256>>>(x, Wev0, bev0, ew0);

    static int smem_set = 0;
    if (!smem_set) {
        cudaFuncSetAttribute(liquid_kernel,
                             cudaFuncAttributeMaxDynamicSharedMemorySize,
                             SMEM_BYTES);
        smem_set = 1;
    }

    liquid_kernel<<<GRID, NT, SMEM_BYTES>>>(
        x, bin0, brec0, battn0, tau0, gamma0, beta0,
        bin1, brec1, battn1, Wev1, bev1, tau1, gamma1, beta1,
        bskip, Wout, bout,
        out, ew0, ew1);
}